// round 10
// baseline (speedup 1.0000x reference)
#include <cuda_runtime.h>
#include <cuda_fp16.h>
#include <mma.h>

using namespace nvcuda;

#define N_NODES 100000
#define N_EDGES 1600000
#define IN_CH   128
#define HID     64
#define SEG     64                     // fixed bucket capacity per node

// ---------------- device scratch (no allocations allowed) ----------------
__device__ int    g_cursor[N_NODES];          // per-node fill count (= degree)
__device__ int    g_ssrc[N_NODES * SEG];      // bucketed edge sources
__device__ __half g_hw[N_NODES * HID];        // gather table A (fp16)
__device__ __half g_hw2[N_NODES * HID];       // gather table B (fp16)
__device__ __half g_W1h[IN_CH * HID];         // fp16 weight tables
__device__ __half g_W2h[HID * HID];
__device__ __half g_W3h[HID * HID];

// ---------------- weight prep: fp32 -> fp16 tables -------------------------
__global__ void k_prep(const float* __restrict__ W1, const float* __restrict__ W2,
                       const float* __restrict__ W3) {
    int i = blockIdx.x * blockDim.x + threadIdx.x;
    if (i < IN_CH * HID) g_W1h[i] = __float2half(__ldg(&W1[i]));
    if (i < HID * HID) {
        g_W2h[i] = __float2half(__ldg(&W2[i]));
        g_W3h[i] = __float2half(__ldg(&W3[i]));
    }
}

// ---------------- bucket scatter -------------------------------------------
__global__ void k_scatter(const int* __restrict__ src, const int* __restrict__ dst) {
    int i = blockIdx.x * blockDim.x + threadIdx.x;
    int e = i * 4;
    if (e + 4 <= N_EDGES) {
        int4 d = __ldg((const int4*)(dst + e));
        int4 s = __ldg((const int4*)(src + e));
        int p;
        p = atomicAdd(&g_cursor[d.x], 1); if (p < SEG) g_ssrc[d.x * SEG + p] = s.x;
        p = atomicAdd(&g_cursor[d.y], 1); if (p < SEG) g_ssrc[d.y * SEG + p] = s.y;
        p = atomicAdd(&g_cursor[d.z], 1); if (p < SEG) g_ssrc[d.z * SEG + p] = s.z;
        p = atomicAdd(&g_cursor[d.w], 1); if (p < SEG) g_ssrc[d.w * SEG + p] = s.w;
    } else {
        for (; e < N_EDGES; e++) {
            int dd = __ldg(&dst[e]);
            int p = atomicAdd(&g_cursor[dd], 1);
            if (p < SEG) g_ssrc[dd * SEG + p] = __ldg(&src[e]);
        }
    }
}

// ---- layer-1 tensor-core transform (256 thr): O = half(X[n,128]) @ W1h ----
__global__ __launch_bounds__(256)
void k_transform_mma128(const float* __restrict__ X, __half* __restrict__ O) {
    extern __shared__ char smraw[];
    const int K = 128, LDA = 144, LDB = 80, LDC = 80;
    __half* sA = (__half*)smraw;              // 64*144 halves
    __half* sB = sA + 64 * LDA;               // 128*80 halves
    float*  sC = (float*)smraw;               // 64*80 floats (overlay)

    const int tid  = threadIdx.x;
    const int warp = tid >> 5;
    const int rowBase = blockIdx.x * 64;

    const uint4* Wh4 = (const uint4*)g_W1h;
    for (int i = tid; i < 128 * 8; i += 256) {
        int r = i >> 3, q = i & 7;
        *(uint4*)(sB + r * LDB + q * 8) = __ldg(&Wh4[i]);
    }
    const float4* X4 = (const float4*)X;
    for (int i = tid; i < 64 * 32; i += 256) {
        int r = i >> 5, q = i & 31;
        int gr = rowBase + r;
        float4 v = (gr < N_NODES) ? __ldg(&X4[(size_t)gr * 32 + q])
                                  : make_float4(0.f, 0.f, 0.f, 0.f);
        union { __half2 h[2]; uint2 u; } p;
        p.h[0] = __floats2half2_rn(v.x, v.y);
        p.h[1] = __floats2half2_rn(v.z, v.w);
        *(uint2*)(sA + r * LDA + q * 4) = p.u;
    }
    __syncthreads();

    const int stripe  = warp >> 1;
    const int colHalf = warp & 1;
    wmma::fragment<wmma::accumulator, 16, 16, 16, float> acc[2];
    wmma::fill_fragment(acc[0], 0.f);
    wmma::fill_fragment(acc[1], 0.f);

    #pragma unroll
    for (int k = 0; k < K; k += 16) {
        wmma::fragment<wmma::matrix_a, 16, 16, 16, __half, wmma::row_major> a;
        wmma::load_matrix_sync(a, sA + stripe * 16 * LDA + k, LDA);
        #pragma unroll
        for (int j = 0; j < 2; j++) {
            wmma::fragment<wmma::matrix_b, 16, 16, 16, __half, wmma::row_major> b;
            wmma::load_matrix_sync(b, sB + k * LDB + colHalf * 32 + j * 16, LDB);
            wmma::mma_sync(acc[j], a, b, acc[j]);
        }
    }
    __syncthreads();

    #pragma unroll
    for (int j = 0; j < 2; j++)
        wmma::store_matrix_sync(sC + stripe * 16 * LDC + colHalf * 32 + j * 16,
                                acc[j], LDC, wmma::mem_row_major);
    __syncthreads();

    for (int i = tid; i < 64 * 8; i += 256) {
        int r = i >> 3, q = i & 7;
        int gr = rowBase + r;
        if (gr < N_NODES) {
            const float* src = &sC[r * LDC + q * 8];
            union { __half2 h[4]; uint4 u; } p;
            p.h[0] = __floats2half2_rn(src[0], src[1]);
            p.h[1] = __floats2half2_rn(src[2], src[3]);
            p.h[2] = __floats2half2_rn(src[4], src[5]);
            p.h[3] = __floats2half2_rn(src[6], src[7]);
            ((uint4*)O)[(size_t)gr * 8 + q] = p.u;
        }
    }
}

// two-node interleaved full-warp gather: doubles loads in flight.
// nA/nB < 0 => skip that node (result {0,0}).
__device__ __forceinline__ void gather_pair(const __half2* __restrict__ hw2,
                                            int nA, int nB, int lane,
                                            float2& outA, float2& outB) {
    int degA = 0, degB = 0, stA = 0, stB = 0;
    if (nA >= 0) { degA = min(__ldg(&g_cursor[nA]), SEG); stA = nA * SEG; }
    if (nB >= 0) { degB = min(__ldg(&g_cursor[nB]), SEG); stB = nB * SEG; }
    const int4* iA = (const int4*)(g_ssrc + stA);
    const int4* iB = (const int4*)(g_ssrc + stB);
    int n4A = degA >> 2, n4B = degB >> 2;
    int nmax = max(n4A, n4B);

    float2 a0 = {0.f,0.f}, a1 = {0.f,0.f};   // node A accums
    float2 b0 = {0.f,0.f}, b1 = {0.f,0.f};   // node B accums

    for (int t = 0; t < nmax; t++) {
        bool doA = (t < n4A), doB = (t < n4B);
        int4 sA4, sB4;
        if (doA) sA4 = __ldg(&iA[t]);
        if (doB) sB4 = __ldg(&iB[t]);
        if (doA) {
            __half2 v0 = __ldg(&hw2[sA4.x * 32 + lane]);
            __half2 v1 = __ldg(&hw2[sA4.y * 32 + lane]);
            __half2 v2 = __ldg(&hw2[sA4.z * 32 + lane]);
            __half2 v3 = __ldg(&hw2[sA4.w * 32 + lane]);
            float2 f01 = __half22float2(__hadd2(v0, v1));
            float2 f23 = __half22float2(__hadd2(v2, v3));
            a0.x += f01.x; a0.y += f01.y;
            a1.x += f23.x; a1.y += f23.y;
        }
        if (doB) {
            __half2 w0 = __ldg(&hw2[sB4.x * 32 + lane]);
            __half2 w1 = __ldg(&hw2[sB4.y * 32 + lane]);
            __half2 w2 = __ldg(&hw2[sB4.z * 32 + lane]);
            __half2 w3 = __ldg(&hw2[sB4.w * 32 + lane]);
            float2 g01 = __half22float2(__hadd2(w0, w1));
            float2 g23 = __half22float2(__hadd2(w2, w3));
            b0.x += g01.x; b0.y += g01.y;
            b1.x += g23.x; b1.y += g23.y;
        }
    }
    for (int e = stA + (n4A << 2); e < stA + degA; e++) {
        int s = __ldg(&g_ssrc[e]);
        float2 v = __half22float2(__ldg(&hw2[s * 32 + lane]));
        a0.x += v.x; a0.y += v.y;
    }
    for (int e = stB + (n4B << 2); e < stB + degB; e++) {
        int s = __ldg(&g_ssrc[e]);
        float2 v = __half22float2(__ldg(&hw2[s * 32 + lane]));
        b0.x += v.x; b0.y += v.y;
    }
    outA = make_float2(a0.x + a1.x, a0.y + a1.y);
    outB = make_float2(b0.x + b1.x, b0.y + b1.y);
}

// ---- fused agg(+bias,relu) -> GEMM(Wh) -> fp16 table (layers 2 and 3) -----
__global__ __launch_bounds__(256)
void k_agg_transform(const __half* __restrict__ HW, const float* __restrict__ bias,
                     const __half* __restrict__ Wh, __half* __restrict__ O) {
    extern __shared__ char smraw[];
    const int LDA = 80, LDB = 80, LDC = 80;
    __half* sA = (__half*)smraw;              // 64*80 halves
    __half* sB = sA + 64 * LDA;               // 64*80 halves
    float*  sC = (float*)smraw;               // 64*80 floats (overlay)

    const int tid  = threadIdx.x;
    const int warp = tid >> 5;
    const int lane = tid & 31;
    const int rowBase = blockIdx.x * 64;

    const uint4* Wh4 = (const uint4*)Wh;
    for (int i = tid; i < 64 * 8; i += 256) {
        int r = i >> 3, q = i & 7;
        *(uint4*)(sB + r * LDB + q * 8) = __ldg(&Wh4[i]);
    }

    const __half2* __restrict__ hw2 = (const __half2*)HW;
    float2 bb = __ldg(&((const float2*)bias)[lane]);
    #pragma unroll 1
    for (int i = 0; i < 4; i++) {                  // 4 node pairs per warp
        int r0 = warp * 8 + i * 2;
        int r1 = r0 + 1;
        int gA = rowBase + r0, gB = rowBase + r1;
        float2 sA2, sB2;
        gather_pair(hw2, (gA < N_NODES) ? gA : -1, (gB < N_NODES) ? gB : -1,
                    lane, sA2, sB2);
        float ax = fmaxf(sA2.x + bb.x, 0.f);
        float ay = fmaxf(sA2.y + bb.y, 0.f);
        float bx = fmaxf(sB2.x + bb.x, 0.f);
        float by = fmaxf(sB2.y + bb.y, 0.f);
        ((__half2*)(sA + r0 * LDA))[lane] = __floats2half2_rn(ax, ay);
        ((__half2*)(sA + r1 * LDA))[lane] = __floats2half2_rn(bx, by);
    }
    __syncthreads();

    const int stripe  = warp >> 1;
    const int colHalf = warp & 1;
    wmma::fragment<wmma::accumulator, 16, 16, 16, float> acc[2];
    wmma::fill_fragment(acc[0], 0.f);
    wmma::fill_fragment(acc[1], 0.f);

    #pragma unroll
    for (int k = 0; k < 64; k += 16) {
        wmma::fragment<wmma::matrix_a, 16, 16, 16, __half, wmma::row_major> a;
        wmma::load_matrix_sync(a, sA + stripe * 16 * LDA + k, LDA);
        #pragma unroll
        for (int j = 0; j < 2; j++) {
            wmma::fragment<wmma::matrix_b, 16, 16, 16, __half, wmma::row_major> b;
            wmma::load_matrix_sync(b, sB + k * LDB + colHalf * 32 + j * 16, LDB);
            wmma::mma_sync(acc[j], a, b, acc[j]);
        }
    }
    __syncthreads();

    #pragma unroll
    for (int j = 0; j < 2; j++)
        wmma::store_matrix_sync(sC + stripe * 16 * LDC + colHalf * 32 + j * 16,
                                acc[j], LDC, wmma::mem_row_major);
    __syncthreads();

    for (int i = tid; i < 64 * 8; i += 256) {
        int r = i >> 3, q = i & 7;
        int gr = rowBase + r;
        if (gr < N_NODES) {
            const float* src = &sC[r * LDC + q * 8];
            union { __half2 h[4]; uint4 u; } p;
            p.h[0] = __floats2half2_rn(src[0], src[1]);
            p.h[1] = __floats2half2_rn(src[2], src[3]);
            p.h[2] = __floats2half2_rn(src[4], src[5]);
            p.h[3] = __floats2half2_rn(src[6], src[7]);
            ((uint4*)O)[(size_t)gr * 8 + q] = p.u;
        }
    }
}

// ---------------- final aggregation (2 nodes/warp interleaved, fp32 out) ---
__global__ __launch_bounds__(256)
void k_agg_final(const __half* __restrict__ HW, const float* __restrict__ bias,
                 float* __restrict__ O) {
    int w = (blockIdx.x * blockDim.x + threadIdx.x) >> 5;
    int lane = threadIdx.x & 31;
    int nA = w * 2;
    int nB = nA + 1;
    if (nA >= N_NODES) return;
    if (nB >= N_NODES) nB = -1;

    const __half2* __restrict__ hw2 = (const __half2*)HW;
    float2 sA2, sB2;
    gather_pair(hw2, nA, nB, lane, sA2, sB2);
    float2 b = __ldg(&((const float2*)bias)[lane]);
    ((float2*)O)[(size_t)nA * 32 + lane] = make_float2(sA2.x + b.x, sA2.y + b.y);
    if (nB >= 0)
        ((float2*)O)[(size_t)nB * 32 + lane] = make_float2(sB2.x + b.x, sB2.y + b.y);
}

// ---------------- launch ----------------
extern "C" void kernel_launch(void* const* d_in, const int* in_sizes, int n_in,
                              void* d_out, int out_size) {
    const float* x    = (const float*)d_in[0];
    const int*   esrc = (const int*)  d_in[1];
    const int*   edst = (const int*)  d_in[2];
    const float* W1   = (const float*)d_in[3];
    const float* b1   = (const float*)d_in[4];
    const float* W2   = (const float*)d_in[5];
    const float* b2   = (const float*)d_in[6];
    const float* W3   = (const float*)d_in[7];
    const float* b3   = (const float*)d_in[8];
    float* out = (float*)d_out;

    void* p_hw_v;  cudaGetSymbolAddress(&p_hw_v,  g_hw);
    void* p_hw2_v; cudaGetSymbolAddress(&p_hw2_v, g_hw2);
    void* p_cur_v; cudaGetSymbolAddress(&p_cur_v, g_cursor);
    void* p_w2h_v; cudaGetSymbolAddress(&p_w2h_v, g_W2h);
    void* p_w3h_v; cudaGetSymbolAddress(&p_w3h_v, g_W3h);
    __half* p_hw  = (__half*)p_hw_v;
    __half* p_hw2 = (__half*)p_hw2_v;
    __half* p_w2h = (__half*)p_w2h_v;
    __half* p_w3h = (__half*)p_w3h_v;

    static cudaStream_t s2 = nullptr;
    static cudaEvent_t evFork = nullptr, evJoin = nullptr;
    if (!s2) {
        cudaStreamCreateWithFlags(&s2, cudaStreamNonBlocking);
        cudaEventCreateWithFlags(&evFork, cudaEventDisableTiming);
        cudaEventCreateWithFlags(&evJoin, cudaEventDisableTiming);
    }

    const int smem128 = 64 * 144 * 2 + 128 * 80 * 2;  // 38,912 B
    const int smemF   = 64 * 80 * 4;                   // 20,480 B
    cudaFuncSetAttribute(k_transform_mma128, cudaFuncAttributeMaxDynamicSharedMemorySize, smem128);
    cudaFuncSetAttribute(k_agg_transform,    cudaFuncAttributeMaxDynamicSharedMemorySize, smemF);

    const int tgrid = (N_NODES + 63) / 64;

    // weight prep first (main stream; tiny)
    k_prep<<<(IN_CH * HID + 255) / 256, 256>>>(W1, W2, W3);

    // ---- fork: bucket scatter on s2, layer-1 transform on main stream ----
    cudaEventRecord(evFork, 0);
    cudaStreamWaitEvent(s2, evFork, 0);

    cudaMemsetAsync(p_cur_v, 0, N_NODES * sizeof(int), s2);
    k_scatter<<<(N_EDGES / 4 + 255) / 256, 256, 0, s2>>>(esrc, edst);
    cudaEventRecord(evJoin, s2);

    k_transform_mma128<<<tgrid, 256, smem128>>>(x, p_hw);

    cudaStreamWaitEvent(0, evJoin, 0);   // join before first aggregation

    // layer 2: agg(hw,+b1,relu) -> @W2 -> hw2
    k_agg_transform<<<tgrid, 256, smemF>>>(p_hw, b1, p_w2h, p_hw2);
    // layer 3: agg(hw2,+b2,relu) -> @W3 -> hw
    k_agg_transform<<<tgrid, 256, smemF>>>(p_hw2, b2, p_w3h, p_hw);
    // final: agg(hw) + b3 -> out (fp32), 2 nodes per warp interleaved
    const int npairs = (N_NODES + 1) / 2;             // 50000 warps
    const int fgrid  = (npairs * 32 + 255) / 256;
    k_agg_final<<<fgrid, 256>>>(p_hw, b3, out);
}

// round 11
// speedup vs baseline: 1.1957x; 1.1957x over previous
#include <cuda_runtime.h>
#include <cuda_fp16.h>
#include <mma.h>

using namespace nvcuda;

#define N_NODES 100000
#define N_EDGES 1600000
#define IN_CH   128
#define HID     64
#define SEG     64                     // fixed bucket capacity per node

// ---------------- device scratch (no allocations allowed) ----------------
__device__ int    g_cursor[N_NODES];          // per-node fill count (= degree)
__device__ int    g_ssrc[N_NODES * SEG];      // bucketed edge sources
__device__ __half g_hw[N_NODES * HID];        // gather table A (fp16)
__device__ __half g_hw2[N_NODES * HID];       // gather table B (fp16)
__device__ __half g_W1h[IN_CH * HID];         // fp16 weight tables
__device__ __half g_W2h[HID * HID];
__device__ __half g_W3h[HID * HID];

// ---------------- weight prep: fp32 -> fp16 tables -------------------------
__global__ void k_prep(const float* __restrict__ W1, const float* __restrict__ W2,
                       const float* __restrict__ W3) {
    int i = blockIdx.x * blockDim.x + threadIdx.x;
    if (i < IN_CH * HID) g_W1h[i] = __float2half(__ldg(&W1[i]));
    if (i < HID * HID) {
        g_W2h[i] = __float2half(__ldg(&W2[i]));
        g_W3h[i] = __float2half(__ldg(&W3[i]));
    }
}

// ---------------- bucket scatter -------------------------------------------
__global__ void k_scatter(const int* __restrict__ src, const int* __restrict__ dst) {
    int i = blockIdx.x * blockDim.x + threadIdx.x;
    int e = i * 4;
    if (e + 4 <= N_EDGES) {
        int4 d = __ldg((const int4*)(dst + e));
        int4 s = __ldg((const int4*)(src + e));
        int p;
        p = atomicAdd(&g_cursor[d.x], 1); if (p < SEG) g_ssrc[d.x * SEG + p] = s.x;
        p = atomicAdd(&g_cursor[d.y], 1); if (p < SEG) g_ssrc[d.y * SEG + p] = s.y;
        p = atomicAdd(&g_cursor[d.z], 1); if (p < SEG) g_ssrc[d.z * SEG + p] = s.z;
        p = atomicAdd(&g_cursor[d.w], 1); if (p < SEG) g_ssrc[d.w * SEG + p] = s.w;
    } else {
        for (; e < N_EDGES; e++) {
            int dd = __ldg(&dst[e]);
            int p = atomicAdd(&g_cursor[dd], 1);
            if (p < SEG) g_ssrc[dd * SEG + p] = __ldg(&src[e]);
        }
    }
}

// ---- layer-1 tensor-core transform (256 thr): O = half(X[n,128]) @ W1h ----
__global__ __launch_bounds__(256)
void k_transform_mma128(const float* __restrict__ X, __half* __restrict__ O) {
    extern __shared__ char smraw[];
    const int K = 128, LDA = 144, LDB = 80, LDC = 80;
    __half* sA = (__half*)smraw;              // 64*144 halves
    __half* sB = sA + 64 * LDA;               // 128*80 halves
    float*  sC = (float*)smraw;               // 64*80 floats (overlay)

    const int tid  = threadIdx.x;
    const int warp = tid >> 5;
    const int rowBase = blockIdx.x * 64;

    const uint4* Wh4 = (const uint4*)g_W1h;
    for (int i = tid; i < 128 * 8; i += 256) {
        int r = i >> 3, q = i & 7;
        *(uint4*)(sB + r * LDB + q * 8) = __ldg(&Wh4[i]);
    }
    const float4* X4 = (const float4*)X;
    for (int i = tid; i < 64 * 32; i += 256) {
        int r = i >> 5, q = i & 31;
        int gr = rowBase + r;
        float4 v = (gr < N_NODES) ? __ldg(&X4[(size_t)gr * 32 + q])
                                  : make_float4(0.f, 0.f, 0.f, 0.f);
        union { __half2 h[2]; uint2 u; } p;
        p.h[0] = __floats2half2_rn(v.x, v.y);
        p.h[1] = __floats2half2_rn(v.z, v.w);
        *(uint2*)(sA + r * LDA + q * 4) = p.u;
    }
    __syncthreads();

    const int stripe  = warp >> 1;
    const int colHalf = warp & 1;
    wmma::fragment<wmma::accumulator, 16, 16, 16, float> acc[2];
    wmma::fill_fragment(acc[0], 0.f);
    wmma::fill_fragment(acc[1], 0.f);

    #pragma unroll
    for (int k = 0; k < K; k += 16) {
        wmma::fragment<wmma::matrix_a, 16, 16, 16, __half, wmma::row_major> a;
        wmma::load_matrix_sync(a, sA + stripe * 16 * LDA + k, LDA);
        #pragma unroll
        for (int j = 0; j < 2; j++) {
            wmma::fragment<wmma::matrix_b, 16, 16, 16, __half, wmma::row_major> b;
            wmma::load_matrix_sync(b, sB + k * LDB + colHalf * 32 + j * 16, LDB);
            wmma::mma_sync(acc[j], a, b, acc[j]);
        }
    }
    __syncthreads();

    #pragma unroll
    for (int j = 0; j < 2; j++)
        wmma::store_matrix_sync(sC + stripe * 16 * LDC + colHalf * 32 + j * 16,
                                acc[j], LDC, wmma::mem_row_major);
    __syncthreads();

    for (int i = tid; i < 64 * 8; i += 256) {
        int r = i >> 3, q = i & 7;
        int gr = rowBase + r;
        if (gr < N_NODES) {
            const float* src = &sC[r * LDC + q * 8];
            union { __half2 h[4]; uint4 u; } p;
            p.h[0] = __floats2half2_rn(src[0], src[1]);
            p.h[1] = __floats2half2_rn(src[2], src[3]);
            p.h[2] = __floats2half2_rn(src[4], src[5]);
            p.h[3] = __floats2half2_rn(src[6], src[7]);
            ((uint4*)O)[(size_t)gr * 8 + q] = p.u;
        }
    }
}

// full-warp gather-sum; indices preloaded to registers (2 coalesced LDG),
// broadcast via shfl -> feature loads have no dependent-load chain.
__device__ __forceinline__ float2 gather_node(const __half2* __restrict__ hw2,
                                              int node, int lane) {
    int deg = min(__ldg(&g_cursor[node]), SEG);
    int base = node * SEG;
    // bucket is always SEG slots: OOB-safe preload of all 64 index slots
    int i0 = __ldg(&g_ssrc[base + lane]);
    int i1 = __ldg(&g_ssrc[base + 32 + lane]);

    float2 a0 = {0.f, 0.f}, a1 = {0.f, 0.f};
    int d0 = min(deg, 32);
    int e = 0;
    #pragma unroll 2
    for (; e + 4 <= d0; e += 4) {
        int s0 = __shfl_sync(0xFFFFFFFFu, i0, e);
        int s1 = __shfl_sync(0xFFFFFFFFu, i0, e + 1);
        int s2 = __shfl_sync(0xFFFFFFFFu, i0, e + 2);
        int s3 = __shfl_sync(0xFFFFFFFFu, i0, e + 3);
        __half2 v0 = __ldg(&hw2[s0 * 32 + lane]);
        __half2 v1 = __ldg(&hw2[s1 * 32 + lane]);
        __half2 v2 = __ldg(&hw2[s2 * 32 + lane]);
        __half2 v3 = __ldg(&hw2[s3 * 32 + lane]);
        float2 f01 = __half22float2(__hadd2(v0, v1));
        float2 f23 = __half22float2(__hadd2(v2, v3));
        a0.x += f01.x; a0.y += f01.y;
        a1.x += f23.x; a1.y += f23.y;
    }
    for (; e < d0; e++) {
        int s = __shfl_sync(0xFFFFFFFFu, i0, e);
        float2 v = __half22float2(__ldg(&hw2[s * 32 + lane]));
        a0.x += v.x; a0.y += v.y;
    }
    e = 32;
    #pragma unroll 2
    for (; e + 4 <= deg; e += 4) {
        int s0 = __shfl_sync(0xFFFFFFFFu, i1, e - 32);
        int s1 = __shfl_sync(0xFFFFFFFFu, i1, e - 31);
        int s2 = __shfl_sync(0xFFFFFFFFu, i1, e - 30);
        int s3 = __shfl_sync(0xFFFFFFFFu, i1, e - 29);
        __half2 v0 = __ldg(&hw2[s0 * 32 + lane]);
        __half2 v1 = __ldg(&hw2[s1 * 32 + lane]);
        __half2 v2 = __ldg(&hw2[s2 * 32 + lane]);
        __half2 v3 = __ldg(&hw2[s3 * 32 + lane]);
        float2 f01 = __half22float2(__hadd2(v0, v1));
        float2 f23 = __half22float2(__hadd2(v2, v3));
        a0.x += f01.x; a0.y += f01.y;
        a1.x += f23.x; a1.y += f23.y;
    }
    for (; e < deg; e++) {
        int s = __shfl_sync(0xFFFFFFFFu, i1, e - 32);
        float2 v = __half22float2(__ldg(&hw2[s * 32 + lane]));
        a0.x += v.x; a0.y += v.y;
    }
    return make_float2(a0.x + a1.x, a0.y + a1.y);
}

// ---- fused agg(+bias,relu) -> GEMM(Wh) -> fp16 table (layers 2 and 3) -----
__global__ __launch_bounds__(256)
void k_agg_transform(const __half* __restrict__ HW, const float* __restrict__ bias,
                     const __half* __restrict__ Wh, __half* __restrict__ O) {
    extern __shared__ char smraw[];
    const int LDA = 80, LDB = 80, LDC = 80;
    __half* sA = (__half*)smraw;              // 64*80 halves
    __half* sB = sA + 64 * LDA;               // 64*80 halves
    float*  sC = (float*)smraw;               // 64*80 floats (overlay)

    const int tid  = threadIdx.x;
    const int warp = tid >> 5;
    const int lane = tid & 31;
    const int rowBase = blockIdx.x * 64;

    const uint4* Wh4 = (const uint4*)Wh;
    for (int i = tid; i < 64 * 8; i += 256) {
        int r = i >> 3, q = i & 7;
        *(uint4*)(sB + r * LDB + q * 8) = __ldg(&Wh4[i]);
    }

    const __half2* __restrict__ hw2 = (const __half2*)HW;
    float2 bb = __ldg(&((const float2*)bias)[lane]);
    #pragma unroll 1
    for (int i = 0; i < 8; i++) {
        int r  = warp * 8 + i;
        int gr = rowBase + r;
        float2 s = {0.f, 0.f};
        if (gr < N_NODES) s = gather_node(hw2, gr, lane);
        float rx = fmaxf(s.x + bb.x, 0.f);
        float ry = fmaxf(s.y + bb.y, 0.f);
        ((__half2*)(sA + r * LDA))[lane] = __floats2half2_rn(rx, ry);
    }
    __syncthreads();

    const int stripe  = warp >> 1;
    const int colHalf = warp & 1;
    wmma::fragment<wmma::accumulator, 16, 16, 16, float> acc[2];
    wmma::fill_fragment(acc[0], 0.f);
    wmma::fill_fragment(acc[1], 0.f);

    #pragma unroll
    for (int k = 0; k < 64; k += 16) {
        wmma::fragment<wmma::matrix_a, 16, 16, 16, __half, wmma::row_major> a;
        wmma::load_matrix_sync(a, sA + stripe * 16 * LDA + k, LDA);
        #pragma unroll
        for (int j = 0; j < 2; j++) {
            wmma::fragment<wmma::matrix_b, 16, 16, 16, __half, wmma::row_major> b;
            wmma::load_matrix_sync(b, sB + k * LDB + colHalf * 32 + j * 16, LDB);
            wmma::mma_sync(acc[j], a, b, acc[j]);
        }
    }
    __syncthreads();

    #pragma unroll
    for (int j = 0; j < 2; j++)
        wmma::store_matrix_sync(sC + stripe * 16 * LDC + colHalf * 32 + j * 16,
                                acc[j], LDC, wmma::mem_row_major);
    __syncthreads();

    for (int i = tid; i < 64 * 8; i += 256) {
        int r = i >> 3, q = i & 7;
        int gr = rowBase + r;
        if (gr < N_NODES) {
            const float* src = &sC[r * LDC + q * 8];
            union { __half2 h[4]; uint4 u; } p;
            p.h[0] = __floats2half2_rn(src[0], src[1]);
            p.h[1] = __floats2half2_rn(src[2], src[3]);
            p.h[2] = __floats2half2_rn(src[4], src[5]);
            p.h[3] = __floats2half2_rn(src[6], src[7]);
            ((uint4*)O)[(size_t)gr * 8 + q] = p.u;
        }
    }
}

// ---------------- final aggregation (1 node/warp, fp32 out) ----------------
__global__ __launch_bounds__(256)
void k_agg_final(const __half* __restrict__ HW, const float* __restrict__ bias,
                 float* __restrict__ O) {
    int node = (blockIdx.x * blockDim.x + threadIdx.x) >> 5;
    int lane = threadIdx.x & 31;
    if (node >= N_NODES) return;

    const __half2* __restrict__ hw2 = (const __half2*)HW;
    float2 s = gather_node(hw2, node, lane);
    float2 b = __ldg(&((const float2*)bias)[lane]);
    ((float2*)O)[(size_t)node * 32 + lane] = make_float2(s.x + b.x, s.y + b.y);
}

// ---------------- launch ----------------
extern "C" void kernel_launch(void* const* d_in, const int* in_sizes, int n_in,
                              void* d_out, int out_size) {
    const float* x    = (const float*)d_in[0];
    const int*   esrc = (const int*)  d_in[1];
    const int*   edst = (const int*)  d_in[2];
    const float* W1   = (const float*)d_in[3];
    const float* b1   = (const float*)d_in[4];
    const float* W2   = (const float*)d_in[5];
    const float* b2   = (const float*)d_in[6];
    const float* W3   = (const float*)d_in[7];
    const float* b3   = (const float*)d_in[8];
    float* out = (float*)d_out;

    void* p_hw_v;  cudaGetSymbolAddress(&p_hw_v,  g_hw);
    void* p_hw2_v; cudaGetSymbolAddress(&p_hw2_v, g_hw2);
    void* p_cur_v; cudaGetSymbolAddress(&p_cur_v, g_cursor);
    void* p_w2h_v; cudaGetSymbolAddress(&p_w2h_v, g_W2h);
    void* p_w3h_v; cudaGetSymbolAddress(&p_w3h_v, g_W3h);
    __half* p_hw  = (__half*)p_hw_v;
    __half* p_hw2 = (__half*)p_hw2_v;
    __half* p_w2h = (__half*)p_w2h_v;
    __half* p_w3h = (__half*)p_w3h_v;

    static cudaStream_t s2 = nullptr;
    static cudaEvent_t evFork = nullptr, evJoin = nullptr;
    if (!s2) {
        cudaStreamCreateWithFlags(&s2, cudaStreamNonBlocking);
        cudaEventCreateWithFlags(&evFork, cudaEventDisableTiming);
        cudaEventCreateWithFlags(&evJoin, cudaEventDisableTiming);
    }

    const int smem128 = 64 * 144 * 2 + 128 * 80 * 2;  // 38,912 B
    const int smemF   = 64 * 80 * 4;                   // 20,480 B
    cudaFuncSetAttribute(k_transform_mma128, cudaFuncAttributeMaxDynamicSharedMemorySize, smem128);
    cudaFuncSetAttribute(k_agg_transform,    cudaFuncAttributeMaxDynamicSharedMemorySize, smemF);

    const int tgrid = (N_NODES + 63) / 64;
    const int agrid = (N_NODES + 7) / 8;

    // weight prep first (main stream; tiny)
    k_prep<<<(IN_CH * HID + 255) / 256, 256>>>(W1, W2, W3);

    // ---- fork: bucket scatter on s2, layer-1 transform on main stream ----
    cudaEventRecord(evFork, 0);
    cudaStreamWaitEvent(s2, evFork, 0);

    cudaMemsetAsync(p_cur_v, 0, N_NODES * sizeof(int), s2);
    k_scatter<<<(N_EDGES / 4 + 255) / 256, 256, 0, s2>>>(esrc, edst);
    cudaEventRecord(evJoin, s2);

    k_transform_mma128<<<tgrid, 256, smem128>>>(x, p_hw);

    cudaStreamWaitEvent(0, evJoin, 0);   // join before first aggregation

    // layer 2: agg(hw,+b1,relu) -> @W2 -> hw2
    k_agg_transform<<<tgrid, 256, smemF>>>(p_hw, b1, p_w2h, p_hw2);
    // layer 3: agg(hw2,+b2,relu) -> @W3 -> hw
    k_agg_transform<<<tgrid, 256, smemF>>>(p_hw2, b2, p_w3h, p_hw);
    // final: agg(hw) + b3 -> out (fp32)
    k_agg_final<<<agrid, 256>>>(p_hw, b3, out);
}

// round 12
// speedup vs baseline: 1.2536x; 1.0485x over previous
#include <cuda_runtime.h>
#include <cuda_fp16.h>
#include <mma.h>

using namespace nvcuda;

#define N_NODES 100000
#define N_EDGES 1600000
#define IN_CH   128
#define HID     64
#define SEG     64                     // fixed bucket capacity per node

// ---------------- device scratch (no allocations allowed) ----------------
__device__ int    g_cursor[N_NODES];          // per-node fill count (= degree)
__device__ int    g_ssrc[N_NODES * SEG];      // bucketed edge sources
__device__ __half g_hw[N_NODES * HID];        // gather table A (fp16)
__device__ __half g_hw2[N_NODES * HID];       // gather table B (fp16)
__device__ __half g_W1h[IN_CH * HID];         // fp16 weight tables
__device__ __half g_W2h[HID * HID];
__device__ __half g_W3h[HID * HID];

// ---------------- weight prep: fp32 -> fp16 tables -------------------------
__global__ void k_prep(const float* __restrict__ W1, const float* __restrict__ W2,
                       const float* __restrict__ W3) {
    int i = blockIdx.x * blockDim.x + threadIdx.x;
    if (i < IN_CH * HID) g_W1h[i] = __float2half(__ldg(&W1[i]));
    if (i < HID * HID) {
        g_W2h[i] = __float2half(__ldg(&W2[i]));
        g_W3h[i] = __float2half(__ldg(&W3[i]));
    }
}

// ---------------- bucket scatter -------------------------------------------
__global__ void k_scatter(const int* __restrict__ src, const int* __restrict__ dst) {
    int i = blockIdx.x * blockDim.x + threadIdx.x;
    int e = i * 4;
    if (e + 4 <= N_EDGES) {
        int4 d = __ldg((const int4*)(dst + e));
        int4 s = __ldg((const int4*)(src + e));
        int p;
        p = atomicAdd(&g_cursor[d.x], 1); if (p < SEG) g_ssrc[d.x * SEG + p] = s.x;
        p = atomicAdd(&g_cursor[d.y], 1); if (p < SEG) g_ssrc[d.y * SEG + p] = s.y;
        p = atomicAdd(&g_cursor[d.z], 1); if (p < SEG) g_ssrc[d.z * SEG + p] = s.z;
        p = atomicAdd(&g_cursor[d.w], 1); if (p < SEG) g_ssrc[d.w * SEG + p] = s.w;
    } else {
        for (; e < N_EDGES; e++) {
            int dd = __ldg(&dst[e]);
            int p = atomicAdd(&g_cursor[dd], 1);
            if (p < SEG) g_ssrc[dd * SEG + p] = __ldg(&src[e]);
        }
    }
}

// ---- layer-1 tensor-core transform (256 thr): O = half(X[n,128]) @ W1h ----
__global__ __launch_bounds__(256)
void k_transform_mma128(const float* __restrict__ X, __half* __restrict__ O) {
    extern __shared__ char smraw[];
    const int K = 128, LDA = 144, LDB = 80, LDC = 80;
    __half* sA = (__half*)smraw;              // 64*144 halves
    __half* sB = sA + 64 * LDA;               // 128*80 halves
    float*  sC = (float*)smraw;               // 64*80 floats (overlay)

    const int tid  = threadIdx.x;
    const int warp = tid >> 5;
    const int rowBase = blockIdx.x * 64;

    const uint4* Wh4 = (const uint4*)g_W1h;
    for (int i = tid; i < 128 * 8; i += 256) {
        int r = i >> 3, q = i & 7;
        *(uint4*)(sB + r * LDB + q * 8) = __ldg(&Wh4[i]);
    }
    const float4* X4 = (const float4*)X;
    for (int i = tid; i < 64 * 32; i += 256) {
        int r = i >> 5, q = i & 31;
        int gr = rowBase + r;
        float4 v = (gr < N_NODES) ? __ldg(&X4[(size_t)gr * 32 + q])
                                  : make_float4(0.f, 0.f, 0.f, 0.f);
        union { __half2 h[2]; uint2 u; } p;
        p.h[0] = __floats2half2_rn(v.x, v.y);
        p.h[1] = __floats2half2_rn(v.z, v.w);
        *(uint2*)(sA + r * LDA + q * 4) = p.u;
    }
    __syncthreads();

    const int stripe  = warp >> 1;
    const int colHalf = warp & 1;
    wmma::fragment<wmma::accumulator, 16, 16, 16, float> acc[2];
    wmma::fill_fragment(acc[0], 0.f);
    wmma::fill_fragment(acc[1], 0.f);

    #pragma unroll
    for (int k = 0; k < K; k += 16) {
        wmma::fragment<wmma::matrix_a, 16, 16, 16, __half, wmma::row_major> a;
        wmma::load_matrix_sync(a, sA + stripe * 16 * LDA + k, LDA);
        #pragma unroll
        for (int j = 0; j < 2; j++) {
            wmma::fragment<wmma::matrix_b, 16, 16, 16, __half, wmma::row_major> b;
            wmma::load_matrix_sync(b, sB + k * LDB + colHalf * 32 + j * 16, LDB);
            wmma::mma_sync(acc[j], a, b, acc[j]);
        }
    }
    __syncthreads();

    #pragma unroll
    for (int j = 0; j < 2; j++)
        wmma::store_matrix_sync(sC + stripe * 16 * LDC + colHalf * 32 + j * 16,
                                acc[j], LDC, wmma::mem_row_major);
    __syncthreads();

    for (int i = tid; i < 64 * 8; i += 256) {
        int r = i >> 3, q = i & 7;
        int gr = rowBase + r;
        if (gr < N_NODES) {
            const float* src = &sC[r * LDC + q * 8];
            union { __half2 h[4]; uint4 u; } p;
            p.h[0] = __floats2half2_rn(src[0], src[1]);
            p.h[1] = __floats2half2_rn(src[2], src[3]);
            p.h[2] = __floats2half2_rn(src[4], src[5]);
            p.h[3] = __floats2half2_rn(src[6], src[7]);
            ((uint4*)O)[(size_t)gr * 8 + q] = p.u;
        }
    }
}

// even/odd half-warp gather of ONE node: lanes 0-15 process even edges,
// lanes 16-31 odd edges; each lane loads uint2 (4 channels). Uniform loop
// bound (same node both halves) => no divergence. Per 4 edges: 1 idx LDG +
// 2 feature LDG warp-wide. Returns channels [4*laneIn, 4*laneIn+4) in acc,
// valid in ALL lanes after the xor-combine.
__device__ __forceinline__ float4 gather_node(const uint2* __restrict__ hw4,
                                              int node, int half, int laneIn) {
    int deg = min(__ldg(&g_cursor[node]), SEG);
    int base = node * SEG;
    const int4* idx4 = (const int4*)(g_ssrc + base);
    int n4 = deg >> 2;

    float4 acc = {0.f, 0.f, 0.f, 0.f};
    #pragma unroll 2
    for (int t = 0; t < n4; t++) {
        int4 s = __ldg(&idx4[t]);
        int sa = half ? s.y : s.x;     // this half's first edge
        int sb = half ? s.w : s.z;     // this half's second edge
        uint2 ua = __ldg(&hw4[sa * 16 + laneIn]);
        uint2 ub = __ldg(&hw4[sb * 16 + laneIn]);
        union { uint2 u; __half2 h[2]; } ca{ua}, cb{ub};
        float2 f0 = __half22float2(__hadd2(ca.h[0], cb.h[0]));
        float2 f1 = __half22float2(__hadd2(ca.h[1], cb.h[1]));
        acc.x += f0.x; acc.y += f0.y;
        acc.z += f1.x; acc.w += f1.y;
    }
    // tail (<=3 edges): processed by half 0 only
    for (int e = base + (n4 << 2); e < base + deg; e++) {
        int s = __ldg(&g_ssrc[e]);
        if (half == 0) {
            uint2 u = __ldg(&hw4[s * 16 + laneIn]);
            union { uint2 u; __half2 h[2]; } c{u};
            float2 f0 = __half22float2(c.h[0]);
            float2 f1 = __half22float2(c.h[1]);
            acc.x += f0.x; acc.y += f0.y;
            acc.z += f1.x; acc.w += f1.y;
        }
    }
    // combine even/odd halves (lane L <-> lane L^16 hold same channels)
    acc.x += __shfl_xor_sync(0xFFFFFFFFu, acc.x, 16);
    acc.y += __shfl_xor_sync(0xFFFFFFFFu, acc.y, 16);
    acc.z += __shfl_xor_sync(0xFFFFFFFFu, acc.z, 16);
    acc.w += __shfl_xor_sync(0xFFFFFFFFu, acc.w, 16);
    return acc;
}

// ---- fused agg(+bias,relu) -> GEMM(Wh) -> fp16 table (layers 2 and 3) -----
__global__ __launch_bounds__(256)
void k_agg_transform(const __half* __restrict__ HW, const float* __restrict__ bias,
                     const __half* __restrict__ Wh, __half* __restrict__ O) {
    extern __shared__ char smraw[];
    const int LDA = 80, LDB = 80, LDC = 80;
    __half* sA = (__half*)smraw;              // 64*80 halves
    __half* sB = sA + 64 * LDA;               // 64*80 halves
    float*  sC = (float*)smraw;               // 64*80 floats (overlay)

    const int tid    = threadIdx.x;
    const int warp   = tid >> 5;
    const int lane   = tid & 31;
    const int half   = lane >> 4;
    const int laneIn = lane & 15;
    const int rowBase = blockIdx.x * 64;

    const uint4* Wh4 = (const uint4*)Wh;
    for (int i = tid; i < 64 * 8; i += 256) {
        int r = i >> 3, q = i & 7;
        *(uint4*)(sB + r * LDB + q * 8) = __ldg(&Wh4[i]);
    }

    const uint2* __restrict__ hw4 = (const uint2*)HW;
    // this lane's 2 channels: 4*laneIn + 2*half
    float2 bb = __ldg(&((const float2*)bias)[laneIn * 2 + half]);
    #pragma unroll 1
    for (int i = 0; i < 8; i++) {
        int r  = warp * 8 + i;
        int gr = rowBase + r;
        float4 s = {0.f, 0.f, 0.f, 0.f};
        if (gr < N_NODES) s = gather_node(hw4, gr, half, laneIn);
        float vx = half ? s.z : s.x;
        float vy = half ? s.w : s.y;
        float rx = fmaxf(vx + bb.x, 0.f);
        float ry = fmaxf(vy + bb.y, 0.f);
        ((__half2*)(sA + r * LDA))[laneIn * 2 + half] = __floats2half2_rn(rx, ry);
    }
    __syncthreads();

    const int stripe  = warp >> 1;
    const int colHalf = warp & 1;
    wmma::fragment<wmma::accumulator, 16, 16, 16, float> acc[2];
    wmma::fill_fragment(acc[0], 0.f);
    wmma::fill_fragment(acc[1], 0.f);

    #pragma unroll
    for (int k = 0; k < 64; k += 16) {
        wmma::fragment<wmma::matrix_a, 16, 16, 16, __half, wmma::row_major> a;
        wmma::load_matrix_sync(a, sA + stripe * 16 * LDA + k, LDA);
        #pragma unroll
        for (int j = 0; j < 2; j++) {
            wmma::fragment<wmma::matrix_b, 16, 16, 16, __half, wmma::row_major> b;
            wmma::load_matrix_sync(b, sB + k * LDB + colHalf * 32 + j * 16, LDB);
            wmma::mma_sync(acc[j], a, b, acc[j]);
        }
    }
    __syncthreads();

    #pragma unroll
    for (int j = 0; j < 2; j++)
        wmma::store_matrix_sync(sC + stripe * 16 * LDC + colHalf * 32 + j * 16,
                                acc[j], LDC, wmma::mem_row_major);
    __syncthreads();

    for (int i = tid; i < 64 * 8; i += 256) {
        int r = i >> 3, q = i & 7;
        int gr = rowBase + r;
        if (gr < N_NODES) {
            const float* src = &sC[r * LDC + q * 8];
            union { __half2 h[4]; uint4 u; } p;
            p.h[0] = __floats2half2_rn(src[0], src[1]);
            p.h[1] = __floats2half2_rn(src[2], src[3]);
            p.h[2] = __floats2half2_rn(src[4], src[5]);
            p.h[3] = __floats2half2_rn(src[6], src[7]);
            ((uint4*)O)[(size_t)gr * 8 + q] = p.u;
        }
    }
}

// ---------------- final aggregation (1 node/warp, fp32 out) ----------------
__global__ __launch_bounds__(256)
void k_agg_final(const __half* __restrict__ HW, const float* __restrict__ bias,
                 float* __restrict__ O) {
    int node = (blockIdx.x * blockDim.x + threadIdx.x) >> 5;
    int lane   = threadIdx.x & 31;
    int half   = lane >> 4;
    int laneIn = lane & 15;
    if (node >= N_NODES) return;

    const uint2* __restrict__ hw4 = (const uint2*)HW;
    float4 s = gather_node(hw4, node, half, laneIn);
    float2 b = __ldg(&((const float2*)bias)[laneIn * 2 + half]);
    float vx = half ? s.z : s.x;
    float vy = half ? s.w : s.y;
    ((float2*)O)[(size_t)node * 32 + laneIn * 2 + half] =
        make_float2(vx + b.x, vy + b.y);
}

// ---------------- launch ----------------
extern "C" void kernel_launch(void* const* d_in, const int* in_sizes, int n_in,
                              void* d_out, int out_size) {
    const float* x    = (const float*)d_in[0];
    const int*   esrc = (const int*)  d_in[1];
    const int*   edst = (const int*)  d_in[2];
    const float* W1   = (const float*)d_in[3];
    const float* b1   = (const float*)d_in[4];
    const float* W2   = (const float*)d_in[5];
    const float* b2   = (const float*)d_in[6];
    const float* W3   = (const float*)d_in[7];
    const float* b3   = (const float*)d_in[8];
    float* out = (float*)d_out;

    void* p_hw_v;  cudaGetSymbolAddress(&p_hw_v,  g_hw);
    void* p_hw2_v; cudaGetSymbolAddress(&p_hw2_v, g_hw2);
    void* p_cur_v; cudaGetSymbolAddress(&p_cur_v, g_cursor);
    void* p_w2h_v; cudaGetSymbolAddress(&p_w2h_v, g_W2h);
    void* p_w3h_v; cudaGetSymbolAddress(&p_w3h_v, g_W3h);
    __half* p_hw  = (__half*)p_hw_v;
    __half* p_hw2 = (__half*)p_hw2_v;
    __half* p_w2h = (__half*)p_w2h_v;
    __half* p_w3h = (__half*)p_w3h_v;

    static cudaStream_t s2 = nullptr;
    static cudaEvent_t evFork = nullptr, evJoin = nullptr;
    if (!s2) {
        cudaStreamCreateWithFlags(&s2, cudaStreamNonBlocking);
        cudaEventCreateWithFlags(&evFork, cudaEventDisableTiming);
        cudaEventCreateWithFlags(&evJoin, cudaEventDisableTiming);
    }

    const int smem128 = 64 * 144 * 2 + 128 * 80 * 2;  // 38,912 B
    const int smemF   = 64 * 80 * 4;                   // 20,480 B
    cudaFuncSetAttribute(k_transform_mma128, cudaFuncAttributeMaxDynamicSharedMemorySize, smem128);
    cudaFuncSetAttribute(k_agg_transform,    cudaFuncAttributeMaxDynamicSharedMemorySize, smemF);

    const int tgrid = (N_NODES + 63) / 64;
    const int agrid = (N_NODES + 7) / 8;

    // weight prep first (main stream; tiny)
    k_prep<<<(IN_CH * HID + 255) / 256, 256>>>(W1, W2, W3);

    // ---- fork: bucket scatter on s2, layer-1 transform on main stream ----
    cudaEventRecord(evFork, 0);
    cudaStreamWaitEvent(s2, evFork, 0);

    cudaMemsetAsync(p_cur_v, 0, N_NODES * sizeof(int), s2);
    k_scatter<<<(N_EDGES / 4 + 255) / 256, 256, 0, s2>>>(esrc, edst);
    cudaEventRecord(evJoin, s2);

    k_transform_mma128<<<tgrid, 256, smem128>>>(x, p_hw);

    cudaStreamWaitEvent(0, evJoin, 0);   // join before first aggregation

    // layer 2: agg(hw,+b1,relu) -> @W2 -> hw2
    k_agg_transform<<<tgrid, 256, smemF>>>(p_hw, b1, p_w2h, p_hw2);
    // layer 3: agg(hw2,+b2,relu) -> @W3 -> hw
    k_agg_transform<<<tgrid, 256, smemF>>>(p_hw2, b2, p_w3h, p_hw);
    // final: agg(hw) + b3 -> out (fp32)
    k_agg_final<<<agrid, 256>>>(p_hw, b3, out);
}

// round 13
// speedup vs baseline: 1.2579x; 1.0034x over previous
#include <cuda_runtime.h>
#include <cuda_fp16.h>
#include <mma.h>

using namespace nvcuda;

#define N_NODES 100000
#define N_EDGES 1600000
#define IN_CH   128
#define HID     64
#define SEG     64                     // fixed bucket capacity per node

// ---------------- device scratch (no allocations allowed) ----------------
__device__ int    g_cursor[N_NODES];          // per-node fill count (= degree)
__device__ int    g_ssrc[N_NODES * SEG];      // bucketed edge sources (PRE-SCALED by 32)
__device__ __half g_hw[N_NODES * HID];        // gather table A (fp16)
__device__ __half g_hw2[N_NODES * HID];       // gather table B (fp16)
__device__ __half g_W1h[IN_CH * HID];         // fp16 weight tables
__device__ __half g_W2h[HID * HID];
__device__ __half g_W3h[HID * HID];

// ---------------- weight prep: fp32 -> fp16 tables -------------------------
__global__ void k_prep(const float* __restrict__ W1, const float* __restrict__ W2,
                       const float* __restrict__ W3) {
    int i = blockIdx.x * blockDim.x + threadIdx.x;
    if (i < IN_CH * HID) g_W1h[i] = __float2half(__ldg(&W1[i]));
    if (i < HID * HID) {
        g_W2h[i] = __float2half(__ldg(&W2[i]));
        g_W3h[i] = __float2half(__ldg(&W3[i]));
    }
}

// ---------------- bucket scatter (stores src*32 = __half2-row offset) ------
__global__ void k_scatter(const int* __restrict__ src, const int* __restrict__ dst) {
    int i = blockIdx.x * blockDim.x + threadIdx.x;
    int e = i * 4;
    if (e + 4 <= N_EDGES) {
        int4 d = __ldg((const int4*)(dst + e));
        int4 s = __ldg((const int4*)(src + e));
        int p;
        p = atomicAdd(&g_cursor[d.x], 1); if (p < SEG) g_ssrc[d.x * SEG + p] = s.x * 32;
        p = atomicAdd(&g_cursor[d.y], 1); if (p < SEG) g_ssrc[d.y * SEG + p] = s.y * 32;
        p = atomicAdd(&g_cursor[d.z], 1); if (p < SEG) g_ssrc[d.z * SEG + p] = s.z * 32;
        p = atomicAdd(&g_cursor[d.w], 1); if (p < SEG) g_ssrc[d.w * SEG + p] = s.w * 32;
    } else {
        for (; e < N_EDGES; e++) {
            int dd = __ldg(&dst[e]);
            int p = atomicAdd(&g_cursor[dd], 1);
            if (p < SEG) g_ssrc[dd * SEG + p] = __ldg(&src[e]) * 32;
        }
    }
}

// ---- layer-1 tensor-core transform (256 thr): O = half(X[n,128]) @ W1h ----
__global__ __launch_bounds__(256)
void k_transform_mma128(const float* __restrict__ X, __half* __restrict__ O) {
    extern __shared__ char smraw[];
    const int K = 128, LDA = 144, LDB = 80, LDC = 80;
    __half* sA = (__half*)smraw;              // 64*144 halves
    __half* sB = sA + 64 * LDA;               // 128*80 halves
    float*  sC = (float*)smraw;               // 64*80 floats (overlay)

    const int tid  = threadIdx.x;
    const int warp = tid >> 5;
    const int rowBase = blockIdx.x * 64;

    const uint4* Wh4 = (const uint4*)g_W1h;
    for (int i = tid; i < 128 * 8; i += 256) {
        int r = i >> 3, q = i & 7;
        *(uint4*)(sB + r * LDB + q * 8) = __ldg(&Wh4[i]);
    }
    const float4* X4 = (const float4*)X;
    for (int i = tid; i < 64 * 32; i += 256) {
        int r = i >> 5, q = i & 31;
        int gr = rowBase + r;
        float4 v = (gr < N_NODES) ? __ldg(&X4[(size_t)gr * 32 + q])
                                  : make_float4(0.f, 0.f, 0.f, 0.f);
        union { __half2 h[2]; uint2 u; } p;
        p.h[0] = __floats2half2_rn(v.x, v.y);
        p.h[1] = __floats2half2_rn(v.z, v.w);
        *(uint2*)(sA + r * LDA + q * 4) = p.u;
    }
    __syncthreads();

    const int stripe  = warp >> 1;
    const int colHalf = warp & 1;
    wmma::fragment<wmma::accumulator, 16, 16, 16, float> acc[2];
    wmma::fill_fragment(acc[0], 0.f);
    wmma::fill_fragment(acc[1], 0.f);

    #pragma unroll
    for (int k = 0; k < K; k += 16) {
        wmma::fragment<wmma::matrix_a, 16, 16, 16, __half, wmma::row_major> a;
        wmma::load_matrix_sync(a, sA + stripe * 16 * LDA + k, LDA);
        #pragma unroll
        for (int j = 0; j < 2; j++) {
            wmma::fragment<wmma::matrix_b, 16, 16, 16, __half, wmma::row_major> b;
            wmma::load_matrix_sync(b, sB + k * LDB + colHalf * 32 + j * 16, LDB);
            wmma::mma_sync(acc[j], a, b, acc[j]);
        }
    }
    __syncthreads();

    #pragma unroll
    for (int j = 0; j < 2; j++)
        wmma::store_matrix_sync(sC + stripe * 16 * LDC + colHalf * 32 + j * 16,
                                acc[j], LDC, wmma::mem_row_major);
    __syncthreads();

    for (int i = tid; i < 64 * 8; i += 256) {
        int r = i >> 3, q = i & 7;
        int gr = rowBase + r;
        if (gr < N_NODES) {
            const float* src = &sC[r * LDC + q * 8];
            union { __half2 h[4]; uint4 u; } p;
            p.h[0] = __floats2half2_rn(src[0], src[1]);
            p.h[1] = __floats2half2_rn(src[2], src[3]);
            p.h[2] = __floats2half2_rn(src[4], src[5]);
            p.h[3] = __floats2half2_rn(src[6], src[7]);
            ((uint4*)O)[(size_t)gr * 8 + q] = p.u;
        }
    }
}

// full-warp gather-sum (R9 structure); indices arrive pre-scaled by 32,
// so feature address is hw2[s + lane] (no IMAD).
__device__ __forceinline__ float2 gather_node(const __half2* __restrict__ hw2,
                                              int node, int lane) {
    int deg = min(__ldg(&g_cursor[node]), SEG);
    int start = node * SEG;
    float2 a0 = {0.f, 0.f}, a1 = {0.f, 0.f};
    const int4* idx4 = (const int4*)(g_ssrc + start);
    int n4 = deg >> 2;
    #pragma unroll 2
    for (int t = 0; t < n4; t++) {
        int4 s = __ldg(&idx4[t]);
        __half2 v0 = __ldg(&hw2[s.x + lane]);
        __half2 v1 = __ldg(&hw2[s.y + lane]);
        __half2 v2 = __ldg(&hw2[s.z + lane]);
        __half2 v3 = __ldg(&hw2[s.w + lane]);
        float2 f01 = __half22float2(__hadd2(v0, v1));
        float2 f23 = __half22float2(__hadd2(v2, v3));
        a0.x += f01.x; a0.y += f01.y;
        a1.x += f23.x; a1.y += f23.y;
    }
    for (int e = start + (n4 << 2); e < start + deg; e++) {
        int s = __ldg(&g_ssrc[e]);
        float2 v = __half22float2(__ldg(&hw2[s + lane]));
        a0.x += v.x; a0.y += v.y;
    }
    return make_float2(a0.x + a1.x, a0.y + a1.y);
}

// ---- fused agg(+bias,relu) -> GEMM(Wh) -> fp16 table (layers 2 and 3) -----
// gather phase uses WORK-STEALING: warps grab rows from a smem counter.
__global__ __launch_bounds__(256)
void k_agg_transform(const __half* __restrict__ HW, const float* __restrict__ bias,
                     const __half* __restrict__ Wh, __half* __restrict__ O) {
    extern __shared__ char smraw[];
    const int LDA = 80, LDB = 80, LDC = 80;
    __half* sA = (__half*)smraw;              // 64*80 halves
    __half* sB = sA + 64 * LDA;               // 64*80 halves
    float*  sC = (float*)smraw;               // 64*80 floats (overlay)
    int* sRow  = (int*)(smraw + 64 * 80 * 4); // work-stealing counter (after sC)

    const int tid  = threadIdx.x;
    const int warp = tid >> 5;
    const int lane = tid & 31;
    const int rowBase = blockIdx.x * 64;

    if (tid == 0) *sRow = 0;

    const uint4* Wh4 = (const uint4*)Wh;
    for (int i = tid; i < 64 * 8; i += 256) {
        int r = i >> 3, q = i & 7;
        *(uint4*)(sB + r * LDB + q * 8) = __ldg(&Wh4[i]);
    }
    __syncthreads();   // counter visible

    const __half2* __restrict__ hw2 = (const __half2*)HW;
    float2 bb = __ldg(&((const float2*)bias)[lane]);
    for (;;) {
        int r;
        if (lane == 0) r = atomicAdd(sRow, 1);
        r = __shfl_sync(0xFFFFFFFFu, r, 0);
        if (r >= 64) break;
        int gr = rowBase + r;
        float2 s = {0.f, 0.f};
        if (gr < N_NODES) s = gather_node(hw2, gr, lane);
        float rx = fmaxf(s.x + bb.x, 0.f);
        float ry = fmaxf(s.y + bb.y, 0.f);
        ((__half2*)(sA + r * LDA))[lane] = __floats2half2_rn(rx, ry);
    }
    __syncthreads();

    const int stripe  = warp >> 1;
    const int colHalf = warp & 1;
    wmma::fragment<wmma::accumulator, 16, 16, 16, float> acc[2];
    wmma::fill_fragment(acc[0], 0.f);
    wmma::fill_fragment(acc[1], 0.f);

    #pragma unroll
    for (int k = 0; k < 64; k += 16) {
        wmma::fragment<wmma::matrix_a, 16, 16, 16, __half, wmma::row_major> a;
        wmma::load_matrix_sync(a, sA + stripe * 16 * LDA + k, LDA);
        #pragma unroll
        for (int j = 0; j < 2; j++) {
            wmma::fragment<wmma::matrix_b, 16, 16, 16, __half, wmma::row_major> b;
            wmma::load_matrix_sync(b, sB + k * LDB + colHalf * 32 + j * 16, LDB);
            wmma::mma_sync(acc[j], a, b, acc[j]);
        }
    }
    __syncthreads();

    #pragma unroll
    for (int j = 0; j < 2; j++)
        wmma::store_matrix_sync(sC + stripe * 16 * LDC + colHalf * 32 + j * 16,
                                acc[j], LDC, wmma::mem_row_major);
    __syncthreads();

    for (int i = tid; i < 64 * 8; i += 256) {
        int r = i >> 3, q = i & 7;
        int gr = rowBase + r;
        if (gr < N_NODES) {
            const float* src = &sC[r * LDC + q * 8];
            union { __half2 h[4]; uint4 u; } p;
            p.h[0] = __floats2half2_rn(src[0], src[1]);
            p.h[1] = __floats2half2_rn(src[2], src[3]);
            p.h[2] = __floats2half2_rn(src[4], src[5]);
            p.h[3] = __floats2half2_rn(src[6], src[7]);
            ((uint4*)O)[(size_t)gr * 8 + q] = p.u;
        }
    }
}

// ---------------- final aggregation (1 node/warp, fp32 out) ----------------
__global__ __launch_bounds__(256)
void k_agg_final(const __half* __restrict__ HW, const float* __restrict__ bias,
                 float* __restrict__ O) {
    int node = (blockIdx.x * blockDim.x + threadIdx.x) >> 5;
    int lane = threadIdx.x & 31;
    if (node >= N_NODES) return;

    const __half2* __restrict__ hw2 = (const __half2*)HW;
    float2 s = gather_node(hw2, node, lane);
    float2 b = __ldg(&((const float2*)bias)[lane]);
    ((float2*)O)[(size_t)node * 32 + lane] = make_float2(s.x + b.x, s.y + b.y);
}

// ---------------- launch ----------------
extern "C" void kernel_launch(void* const* d_in, const int* in_sizes, int n_in,
                              void* d_out, int out_size) {
    const float* x    = (const float*)d_in[0];
    const int*   esrc = (const int*)  d_in[1];
    const int*   edst = (const int*)  d_in[2];
    const float* W1   = (const float*)d_in[3];
    const float* b1   = (const float*)d_in[4];
    const float* W2   = (const float*)d_in[5];
    const float* b2   = (const float*)d_in[6];
    const float* W3   = (const float*)d_in[7];
    const float* b3   = (const float*)d_in[8];
    float* out = (float*)d_out;

    void* p_hw_v;  cudaGetSymbolAddress(&p_hw_v,  g_hw);
    void* p_hw2_v; cudaGetSymbolAddress(&p_hw2_v, g_hw2);
    void* p_cur_v; cudaGetSymbolAddress(&p_cur_v, g_cursor);
    void* p_w2h_v; cudaGetSymbolAddress(&p_w2h_v, g_W2h);
    void* p_w3h_v; cudaGetSymbolAddress(&p_w3h_v, g_W3h);
    __half* p_hw  = (__half*)p_hw_v;
    __half* p_hw2 = (__half*)p_hw2_v;
    __half* p_w2h = (__half*)p_w2h_v;
    __half* p_w3h = (__half*)p_w3h_v;

    static cudaStream_t s2 = nullptr;
    static cudaEvent_t evFork = nullptr, evJoin = nullptr;
    if (!s2) {
        cudaStreamCreateWithFlags(&s2, cudaStreamNonBlocking);
        cudaEventCreateWithFlags(&evFork, cudaEventDisableTiming);
        cudaEventCreateWithFlags(&evJoin, cudaEventDisableTiming);
    }

    const int smem128 = 64 * 144 * 2 + 128 * 80 * 2;  // 38,912 B
    const int smemF   = 64 * 80 * 4 + 16;              // 20,496 B (+ counter)
    cudaFuncSetAttribute(k_transform_mma128, cudaFuncAttributeMaxDynamicSharedMemorySize, smem128);
    cudaFuncSetAttribute(k_agg_transform,    cudaFuncAttributeMaxDynamicSharedMemorySize, smemF);

    const int tgrid = (N_NODES + 63) / 64;
    const int agrid = (N_NODES + 7) / 8;

    // weight prep first (main stream; tiny)
    k_prep<<<(IN_CH * HID + 255) / 256, 256>>>(W1, W2, W3);

    // ---- fork: bucket scatter on s2, layer-1 transform on main stream ----
    cudaEventRecord(evFork, 0);
    cudaStreamWaitEvent(s2, evFork, 0);

    cudaMemsetAsync(p_cur_v, 0, N_NODES * sizeof(int), s2);
    k_scatter<<<(N_EDGES / 4 + 255) / 256, 256, 0, s2>>>(esrc, edst);
    cudaEventRecord(evJoin, s2);

    k_transform_mma128<<<tgrid, 256, smem128>>>(x, p_hw);

    cudaStreamWaitEvent(0, evJoin, 0);   // join before first aggregation

    // layer 2: agg(hw,+b1,relu) -> @W2 -> hw2
    k_agg_transform<<<tgrid, 256, smemF>>>(p_hw, b1, p_w2h, p_hw2);
    // layer 3: agg(hw2,+b2,relu) -> @W3 -> hw
    k_agg_transform<<<tgrid, 256, smemF>>>(p_hw2, b2, p_w3h, p_hw);
    // final: agg(hw) + b3 -> out (fp32)
    k_agg_final<<<agrid, 256>>>(p_hw, b3, out);
}

// round 14
// speedup vs baseline: 1.3448x; 1.0691x over previous
#include <cuda_runtime.h>
#include <cuda_fp16.h>
#include <mma.h>

using namespace nvcuda;

#define N_NODES 100000
#define N_EDGES 1600000
#define IN_CH   128
#define HID     64
#define SEG     64                     // fixed bucket capacity per node

// ---------------- device scratch (no allocations allowed) ----------------
__device__ int    g_cursor[N_NODES];          // per-node fill count (= degree)
__device__ int    g_ssrc[N_NODES * SEG];      // bucketed edge sources (PRE-SCALED by 32)
__device__ __half g_hw[N_NODES * HID];        // gather table A (fp16)
__device__ __half g_hw2[N_NODES * HID];       // gather table B (fp16)
__device__ __half g_W1h[IN_CH * HID];         // fp16 weight tables
__device__ __half g_W2h[HID * HID];
__device__ __half g_W3h[HID * HID];

// ---------------- weight prep: fp32 -> fp16 tables -------------------------
__global__ void k_prep(const float* __restrict__ W1, const float* __restrict__ W2,
                       const float* __restrict__ W3) {
    int i = blockIdx.x * blockDim.x + threadIdx.x;
    if (i < IN_CH * HID) g_W1h[i] = __float2half(__ldg(&W1[i]));
    if (i < HID * HID) {
        g_W2h[i] = __float2half(__ldg(&W2[i]));
        g_W3h[i] = __float2half(__ldg(&W3[i]));
    }
}

// ---------------- bucket scatter (stores src*32 = __half2-row offset) ------
__global__ void k_scatter(const int* __restrict__ src, const int* __restrict__ dst) {
    int i = blockIdx.x * blockDim.x + threadIdx.x;
    int e = i * 4;
    if (e + 4 <= N_EDGES) {
        int4 d = __ldg((const int4*)(dst + e));
        int4 s = __ldg((const int4*)(src + e));
        int p;
        p = atomicAdd(&g_cursor[d.x], 1); if (p < SEG) g_ssrc[d.x * SEG + p] = s.x * 32;
        p = atomicAdd(&g_cursor[d.y], 1); if (p < SEG) g_ssrc[d.y * SEG + p] = s.y * 32;
        p = atomicAdd(&g_cursor[d.z], 1); if (p < SEG) g_ssrc[d.z * SEG + p] = s.z * 32;
        p = atomicAdd(&g_cursor[d.w], 1); if (p < SEG) g_ssrc[d.w * SEG + p] = s.w * 32;
    } else {
        for (; e < N_EDGES; e++) {
            int dd = __ldg(&dst[e]);
            int p = atomicAdd(&g_cursor[dd], 1);
            if (p < SEG) g_ssrc[dd * SEG + p] = __ldg(&src[e]) * 32;
        }
    }
}

// ---- layer-1 transform: 512 thr, 128 rows/block, O = half(X[n,128]) @ W1h -
__global__ __launch_bounds__(512)
void k_transform_mma128(const float* __restrict__ X, __half* __restrict__ O) {
    extern __shared__ char smraw[];
    const int K = 128, LDA = 136, LDB = 72, LDC = 72;
    __half* sA = (__half*)smraw;              // 128*136 halves = 34,816 B
    __half* sB = sA + 128 * LDA;              // 128*72 halves  = 18,432 B
    float*  sC = (float*)smraw;               // 128*72 floats  = 36,864 B (overlay)

    const int tid  = threadIdx.x;
    const int warp = tid >> 5;                // 0..15
    const int rowBase = blockIdx.x * 128;

    // W1h fp16 -> sB (uint4 copies: 128 rows x 8 uint4)
    const uint4* Wh4 = (const uint4*)g_W1h;
    for (int i = tid; i < 128 * 8; i += 512) {
        int r = i >> 3, q = i & 7;
        *(uint4*)(sB + r * LDB + q * 8) = __ldg(&Wh4[i]);
    }
    // X fp32 -> sA half (float4 loads: 128 rows x 32 float4)
    const float4* X4 = (const float4*)X;
    for (int i = tid; i < 128 * 32; i += 512) {
        int r = i >> 5, q = i & 31;
        int gr = rowBase + r;
        float4 v = (gr < N_NODES) ? __ldg(&X4[(size_t)gr * 32 + q])
                                  : make_float4(0.f, 0.f, 0.f, 0.f);
        union { __half2 h[2]; uint2 u; } p;
        p.h[0] = __floats2half2_rn(v.x, v.y);
        p.h[1] = __floats2half2_rn(v.z, v.w);
        *(uint2*)(sA + r * LDA + q * 4) = p.u;
    }
    __syncthreads();

    const int stripe  = warp >> 1;            // 0..7 (16-row stripe)
    const int colHalf = warp & 1;             // 0..1 (32-col half)
    wmma::fragment<wmma::accumulator, 16, 16, 16, float> acc[2];
    wmma::fill_fragment(acc[0], 0.f);
    wmma::fill_fragment(acc[1], 0.f);

    #pragma unroll
    for (int k = 0; k < K; k += 16) {
        wmma::fragment<wmma::matrix_a, 16, 16, 16, __half, wmma::row_major> a;
        wmma::load_matrix_sync(a, sA + stripe * 16 * LDA + k, LDA);
        #pragma unroll
        for (int j = 0; j < 2; j++) {
            wmma::fragment<wmma::matrix_b, 16, 16, 16, __half, wmma::row_major> b;
            wmma::load_matrix_sync(b, sB + k * LDB + colHalf * 32 + j * 16, LDB);
            wmma::mma_sync(acc[j], a, b, acc[j]);
        }
    }
    __syncthreads();

    #pragma unroll
    for (int j = 0; j < 2; j++)
        wmma::store_matrix_sync(sC + stripe * 16 * LDC + colHalf * 32 + j * 16,
                                acc[j], LDC, wmma::mem_row_major);
    __syncthreads();

    for (int i = tid; i < 128 * 8; i += 512) {
        int r = i >> 3, q = i & 7;
        int gr = rowBase + r;
        if (gr < N_NODES) {
            const float* src = &sC[r * LDC + q * 8];
            union { __half2 h[4]; uint4 u; } p;
            p.h[0] = __floats2half2_rn(src[0], src[1]);
            p.h[1] = __floats2half2_rn(src[2], src[3]);
            p.h[2] = __floats2half2_rn(src[4], src[5]);
            p.h[3] = __floats2half2_rn(src[6], src[7]);
            ((uint4*)O)[(size_t)gr * 8 + q] = p.u;
        }
    }
}

// full-warp gather-sum; prescaled indices; depth-2 fp16 add tree per 4 edges.
__device__ __forceinline__ float2 gather_node(const __half2* __restrict__ hw2,
                                              int node, int lane) {
    int deg = min(__ldg(&g_cursor[node]), SEG);
    int start = node * SEG;
    float2 a0 = {0.f, 0.f};
    const int4* idx4 = (const int4*)(g_ssrc + start);
    int n4 = deg >> 2;
    #pragma unroll 2
    for (int t = 0; t < n4; t++) {
        int4 s = __ldg(&idx4[t]);
        __half2 v0 = __ldg(&hw2[s.x + lane]);
        __half2 v1 = __ldg(&hw2[s.y + lane]);
        __half2 v2 = __ldg(&hw2[s.z + lane]);
        __half2 v3 = __ldg(&hw2[s.w + lane]);
        __half2 h = __hadd2(__hadd2(v0, v1), __hadd2(v2, v3));
        float2 f = __half22float2(h);
        a0.x += f.x; a0.y += f.y;
    }
    for (int e = start + (n4 << 2); e < start + deg; e++) {
        int s = __ldg(&g_ssrc[e]);
        float2 v = __half22float2(__ldg(&hw2[s + lane]));
        a0.x += v.x; a0.y += v.y;
    }
    return a0;
}

// ---- fused agg(+bias,relu) -> GEMM(Wh) -> fp16 table (layers 2 and 3) -----
__global__ __launch_bounds__(256)
void k_agg_transform(const __half* __restrict__ HW, const float* __restrict__ bias,
                     const __half* __restrict__ Wh, __half* __restrict__ O) {
    extern __shared__ char smraw[];
    const int LDA = 80, LDB = 80, LDC = 80;
    __half* sA = (__half*)smraw;              // 64*80 halves
    __half* sB = sA + 64 * LDA;               // 64*80 halves
    float*  sC = (float*)smraw;               // 64*80 floats (overlay)

    const int tid  = threadIdx.x;
    const int warp = tid >> 5;
    const int lane = tid & 31;
    const int rowBase = blockIdx.x * 64;

    const uint4* Wh4 = (const uint4*)Wh;
    for (int i = tid; i < 64 * 8; i += 256) {
        int r = i >> 3, q = i & 7;
        *(uint4*)(sB + r * LDB + q * 8) = __ldg(&Wh4[i]);
    }

    const __half2* __restrict__ hw2 = (const __half2*)HW;
    float2 bb = __ldg(&((const float2*)bias)[lane]);
    #pragma unroll 1
    for (int i = 0; i < 8; i++) {
        int r  = warp * 8 + i;
        int gr = rowBase + r;
        float2 s = {0.f, 0.f};
        if (gr < N_NODES) s = gather_node(hw2, gr, lane);
        float rx = fmaxf(s.x + bb.x, 0.f);
        float ry = fmaxf(s.y + bb.y, 0.f);
        ((__half2*)(sA + r * LDA))[lane] = __floats2half2_rn(rx, ry);
    }
    __syncthreads();

    const int stripe  = warp >> 1;
    const int colHalf = warp & 1;
    wmma::fragment<wmma::accumulator, 16, 16, 16, float> acc[2];
    wmma::fill_fragment(acc[0], 0.f);
    wmma::fill_fragment(acc[1], 0.f);

    #pragma unroll
    for (int k = 0; k < 64; k += 16) {
        wmma::fragment<wmma::matrix_a, 16, 16, 16, __half, wmma::row_major> a;
        wmma::load_matrix_sync(a, sA + stripe * 16 * LDA + k, LDA);
        #pragma unroll
        for (int j = 0; j < 2; j++) {
            wmma::fragment<wmma::matrix_b, 16, 16, 16, __half, wmma::row_major> b;
            wmma::load_matrix_sync(b, sB + k * LDB + colHalf * 32 + j * 16, LDB);
            wmma::mma_sync(acc[j], a, b, acc[j]);
        }
    }
    __syncthreads();

    #pragma unroll
    for (int j = 0; j < 2; j++)
        wmma::store_matrix_sync(sC + stripe * 16 * LDC + colHalf * 32 + j * 16,
                                acc[j], LDC, wmma::mem_row_major);
    __syncthreads();

    for (int i = tid; i < 64 * 8; i += 256) {
        int r = i >> 3, q = i & 7;
        int gr = rowBase + r;
        if (gr < N_NODES) {
            const float* src = &sC[r * LDC + q * 8];
            union { __half2 h[4]; uint4 u; } p;
            p.h[0] = __floats2half2_rn(src[0], src[1]);
            p.h[1] = __floats2half2_rn(src[2], src[3]);
            p.h[2] = __floats2half2_rn(src[4], src[5]);
            p.h[3] = __floats2half2_rn(src[6], src[7]);
            ((uint4*)O)[(size_t)gr * 8 + q] = p.u;
        }
    }
}

// ---------------- final aggregation (1 node/warp, fp32 out) ----------------
__global__ __launch_bounds__(256)
void k_agg_final(const __half* __restrict__ HW, const float* __restrict__ bias,
                 float* __restrict__ O) {
    int node = (blockIdx.x * blockDim.x + threadIdx.x) >> 5;
    int lane = threadIdx.x & 31;
    if (node >= N_NODES) return;

    const __half2* __restrict__ hw2 = (const __half2*)HW;
    float2 s = gather_node(hw2, node, lane);
    float2 b = __ldg(&((const float2*)bias)[lane]);
    ((float2*)O)[(size_t)node * 32 + lane] = make_float2(s.x + b.x, s.y + b.y);
}

// ---------------- launch ----------------
extern "C" void kernel_launch(void* const* d_in, const int* in_sizes, int n_in,
                              void* d_out, int out_size) {
    const float* x    = (const float*)d_in[0];
    const int*   esrc = (const int*)  d_in[1];
    const int*   edst = (const int*)  d_in[2];
    const float* W1   = (const float*)d_in[3];
    const float* b1   = (const float*)d_in[4];
    const float* W2   = (const float*)d_in[5];
    const float* b2   = (const float*)d_in[6];
    const float* W3   = (const float*)d_in[7];
    const float* b3   = (const float*)d_in[8];
    float* out = (float*)d_out;

    void* p_hw_v;  cudaGetSymbolAddress(&p_hw_v,  g_hw);
    void* p_hw2_v; cudaGetSymbolAddress(&p_hw2_v, g_hw2);
    void* p_cur_v; cudaGetSymbolAddress(&p_cur_v, g_cursor);
    void* p_w2h_v; cudaGetSymbolAddress(&p_w2h_v, g_W2h);
    void* p_w3h_v; cudaGetSymbolAddress(&p_w3h_v, g_W3h);
    __half* p_hw  = (__half*)p_hw_v;
    __half* p_hw2 = (__half*)p_hw2_v;
    __half* p_w2h = (__half*)p_w2h_v;
    __half* p_w3h = (__half*)p_w3h_v;

    static cudaStream_t s2 = nullptr;
    static cudaEvent_t evFork = nullptr, evJoin = nullptr;
    if (!s2) {
        cudaStreamCreateWithFlags(&s2, cudaStreamNonBlocking);
        cudaEventCreateWithFlags(&evFork, cudaEventDisableTiming);
        cudaEventCreateWithFlags(&evJoin, cudaEventDisableTiming);
    }

    const int smem128 = 128 * 136 * 2 + 128 * 72 * 2;  // 53,248 B
    const int smemF   = 64 * 80 * 4;                    // 20,480 B
    cudaFuncSetAttribute(k_transform_mma128, cudaFuncAttributeMaxDynamicSharedMemorySize, smem128);
    cudaFuncSetAttribute(k_agg_transform,    cudaFuncAttributeMaxDynamicSharedMemorySize, smemF);

    const int tgrid128 = (N_NODES + 127) / 128;   // 782 (layer-1)
    const int tgrid    = (N_NODES + 63) / 64;     // 1563 (fused layers)
    const int agrid    = (N_NODES + 7) / 8;

    // weight prep first (main stream; tiny)
    k_prep<<<(IN_CH * HID + 255) / 256, 256>>>(W1, W2, W3);

    // ---- fork: bucket scatter on s2, layer-1 transform on main stream ----
    cudaEventRecord(evFork, 0);
    cudaStreamWaitEvent(s2, evFork, 0);

    cudaMemsetAsync(p_cur_v, 0, N_NODES * sizeof(int), s2);
    k_scatter<<<(N_EDGES / 4 + 255) / 256, 256, 0, s2>>>(esrc, edst);
    cudaEventRecord(evJoin, s2);

    k_transform_mma128<<<tgrid128, 512, smem128>>>(x, p_hw);

    cudaStreamWaitEvent(0, evJoin, 0);   // join before first aggregation

    // layer 2: agg(hw,+b1,relu) -> @W2 -> hw2
    k_agg_transform<<<tgrid, 256, smemF>>>(p_hw, b1, p_w2h, p_hw2);
    // layer 3: agg(hw2,+b2,relu) -> @W3 -> hw
    k_agg_transform<<<tgrid, 256, smemF>>>(p_hw2, b2, p_w3h, p_hw);
    // final: agg(hw) + b3 -> out (fp32)
    k_agg_final<<<agrid, 256>>>(p_hw, b3, out);
}

// round 15
// speedup vs baseline: 1.3614x; 1.0123x over previous
#include <cuda_runtime.h>
#include <cuda_fp16.h>
#include <mma.h>

using namespace nvcuda;

#define N_NODES 100000
#define N_EDGES 1600000
#define IN_CH   128
#define HID     64
#define SEG     64                     // fixed bucket capacity per node

// ---------------- device scratch (no allocations allowed) ----------------
__device__ int    g_cursor[N_NODES];          // per-node fill count (= degree)
__device__ int    g_ssrc[N_NODES * SEG];      // bucketed edge sources (PRE-SCALED by 32)
__device__ __half g_hw[N_NODES * HID];        // gather table A (fp16)
__device__ __half g_hw2[N_NODES * HID];       // gather table B (fp16)
__device__ __half g_W2h[HID * HID];           // fp16 weight tables (layers 2/3)
__device__ __half g_W3h[HID * HID];

// ---------------- weight prep (W2/W3 only; runs on side stream) ------------
__global__ void k_prep23(const float* __restrict__ W2, const float* __restrict__ W3) {
    int i = blockIdx.x * blockDim.x + threadIdx.x;
    if (i < HID * HID) {
        g_W2h[i] = __float2half(__ldg(&W2[i]));
        g_W3h[i] = __float2half(__ldg(&W3[i]));
    }
}

// ---------------- bucket scatter (stores src*32 = __half2-row offset) ------
__global__ void k_scatter(const int* __restrict__ src, const int* __restrict__ dst) {
    int i = blockIdx.x * blockDim.x + threadIdx.x;
    int e = i * 4;
    if (e + 4 <= N_EDGES) {
        int4 d = __ldg((const int4*)(dst + e));
        int4 s = __ldg((const int4*)(src + e));
        int p;
        p = atomicAdd(&g_cursor[d.x], 1); if (p < SEG) g_ssrc[d.x * SEG + p] = s.x * 32;
        p = atomicAdd(&g_cursor[d.y], 1); if (p < SEG) g_ssrc[d.y * SEG + p] = s.y * 32;
        p = atomicAdd(&g_cursor[d.z], 1); if (p < SEG) g_ssrc[d.z * SEG + p] = s.z * 32;
        p = atomicAdd(&g_cursor[d.w], 1); if (p < SEG) g_ssrc[d.w * SEG + p] = s.w * 32;
    } else {
        for (; e < N_EDGES; e++) {
            int dd = __ldg(&dst[e]);
            int p = atomicAdd(&g_cursor[dd], 1);
            if (p < SEG) g_ssrc[dd * SEG + p] = __ldg(&src[e]) * 32;
        }
    }
}

// ---- layer-1 transform: 512 thr, 128 rows/block, converts W1 itself -------
__global__ __launch_bounds__(512)
void k_transform_mma128(const float* __restrict__ X, const float* __restrict__ W1,
                        __half* __restrict__ O) {
    extern __shared__ char smraw[];
    const int K = 128, LDA = 136, LDB = 72, LDC = 72;
    __half* sA = (__half*)smraw;              // 128*136 halves = 34,816 B
    __half* sB = sA + 128 * LDA;              // 128*72 halves  = 18,432 B
    float*  sC = (float*)smraw;               // 128*72 floats  = 36,864 B (overlay)

    const int tid  = threadIdx.x;
    const int warp = tid >> 5;                // 0..15
    const int rowBase = blockIdx.x * 128;

    // W1 fp32 -> sB half (float4 loads: 128 rows x 16 float4)
    const float4* W4 = (const float4*)W1;
    for (int i = tid; i < 128 * 16; i += 512) {
        int r = i >> 4, q = i & 15;
        float4 v = __ldg(&W4[i]);
        union { __half2 h[2]; uint2 u; } p;
        p.h[0] = __floats2half2_rn(v.x, v.y);
        p.h[1] = __floats2half2_rn(v.z, v.w);
        *(uint2*)(sB + r * LDB + q * 4) = p.u;
    }
    // X fp32 -> sA half (float4 loads: 128 rows x 32 float4)
    const float4* X4 = (const float4*)X;
    for (int i = tid; i < 128 * 32; i += 512) {
        int r = i >> 5, q = i & 31;
        int gr = rowBase + r;
        float4 v = (gr < N_NODES) ? __ldg(&X4[(size_t)gr * 32 + q])
                                  : make_float4(0.f, 0.f, 0.f, 0.f);
        union { __half2 h[2]; uint2 u; } p;
        p.h[0] = __floats2half2_rn(v.x, v.y);
        p.h[1] = __floats2half2_rn(v.z, v.w);
        *(uint2*)(sA + r * LDA + q * 4) = p.u;
    }
    __syncthreads();

    const int stripe  = warp >> 1;            // 0..7 (16-row stripe)
    const int colHalf = warp & 1;             // 0..1 (32-col half)
    wmma::fragment<wmma::accumulator, 16, 16, 16, float> acc[2];
    wmma::fill_fragment(acc[0], 0.f);
    wmma::fill_fragment(acc[1], 0.f);

    #pragma unroll
    for (int k = 0; k < K; k += 16) {
        wmma::fragment<wmma::matrix_a, 16, 16, 16, __half, wmma::row_major> a;
        wmma::load_matrix_sync(a, sA + stripe * 16 * LDA + k, LDA);
        #pragma unroll
        for (int j = 0; j < 2; j++) {
            wmma::fragment<wmma::matrix_b, 16, 16, 16, __half, wmma::row_major> b;
            wmma::load_matrix_sync(b, sB + k * LDB + colHalf * 32 + j * 16, LDB);
            wmma::mma_sync(acc[j], a, b, acc[j]);
        }
    }
    __syncthreads();

    #pragma unroll
    for (int j = 0; j < 2; j++)
        wmma::store_matrix_sync(sC + stripe * 16 * LDC + colHalf * 32 + j * 16,
                                acc[j], LDC, wmma::mem_row_major);
    __syncthreads();

    for (int i = tid; i < 128 * 8; i += 512) {
        int r = i >> 3, q = i & 7;
        int gr = rowBase + r;
        if (gr < N_NODES) {
            const float* src = &sC[r * LDC + q * 8];
            union { __half2 h[4]; uint4 u; } p;
            p.h[0] = __floats2half2_rn(src[0], src[1]);
            p.h[1] = __floats2half2_rn(src[2], src[3]);
            p.h[2] = __floats2half2_rn(src[4], src[5]);
            p.h[3] = __floats2half2_rn(src[6], src[7]);
            ((uint4*)O)[(size_t)gr * 8 + q] = p.u;
        }
    }
}

// full-warp gather-sum; prescaled indices; depth-2 fp16 add tree per 4 edges.
template <int UNROLL>
__device__ __forceinline__ float2 gather_node(const __half2* __restrict__ hw2,
                                              int node, int lane) {
    int deg = min(__ldg(&g_cursor[node]), SEG);
    int start = node * SEG;
    float2 a0 = {0.f, 0.f};
    const int4* idx4 = (const int4*)(g_ssrc + start);
    int n4 = deg >> 2;
    #pragma unroll UNROLL
    for (int t = 0; t < n4; t++) {
        int4 s = __ldg(&idx4[t]);
        __half2 v0 = __ldg(&hw2[s.x + lane]);
        __half2 v1 = __ldg(&hw2[s.y + lane]);
        __half2 v2 = __ldg(&hw2[s.z + lane]);
        __half2 v3 = __ldg(&hw2[s.w + lane]);
        __half2 h = __hadd2(__hadd2(v0, v1), __hadd2(v2, v3));
        float2 f = __half22float2(h);
        a0.x += f.x; a0.y += f.y;
    }
    for (int e = start + (n4 << 2); e < start + deg; e++) {
        int s = __ldg(&g_ssrc[e]);
        float2 v = __half22float2(__ldg(&hw2[s + lane]));
        a0.x += v.x; a0.y += v.y;
    }
    return a0;
}

// ---- fused agg(+bias,relu) -> GEMM(Wh) -> fp16 table (layers 2 and 3) -----
__global__ __launch_bounds__(256)
void k_agg_transform(const __half* __restrict__ HW, const float* __restrict__ bias,
                     const __half* __restrict__ Wh, __half* __restrict__ O) {
    extern __shared__ char smraw[];
    const int LDA = 72, LDB = 72, LDC = 72;
    __half* sA = (__half*)smraw;              // 64*72 halves = 9,216 B
    __half* sB = sA + 64 * LDA;               // 64*72 halves = 9,216 B
    float*  sC = (float*)smraw;               // 64*72 floats = 18,432 B (overlay)

    const int tid  = threadIdx.x;
    const int warp = tid >> 5;
    const int lane = tid & 31;
    const int rowBase = blockIdx.x * 64;

    // Wh fp16 -> sB (uint2 copies: 64 rows x 16 uint2; LDB=72 rows 16B-aligned)
    const uint2* Wh2 = (const uint2*)Wh;
    for (int i = tid; i < 64 * 16; i += 256) {
        int r = i >> 4, q = i & 15;
        *(uint2*)(sB + r * LDB + q * 4) = __ldg(&Wh2[i]);
    }

    const __half2* __restrict__ hw2 = (const __half2*)HW;
    float2 bb = __ldg(&((const float2*)bias)[lane]);
    #pragma unroll 1
    for (int i = 0; i < 8; i++) {
        int r  = warp * 8 + i;
        int gr = rowBase + r;
        float2 s = {0.f, 0.f};
        if (gr < N_NODES) s = gather_node<2>(hw2, gr, lane);
        float rx = fmaxf(s.x + bb.x, 0.f);
        float ry = fmaxf(s.y + bb.y, 0.f);
        ((__half2*)(sA + r * LDA))[lane] = __floats2half2_rn(rx, ry);
    }
    __syncthreads();

    const int stripe  = warp >> 1;
    const int colHalf = warp & 1;
    wmma::fragment<wmma::accumulator, 16, 16, 16, float> acc[2];
    wmma::fill_fragment(acc[0], 0.f);
    wmma::fill_fragment(acc[1], 0.f);

    #pragma unroll
    for (int k = 0; k < 64; k += 16) {
        wmma::fragment<wmma::matrix_a, 16, 16, 16, __half, wmma::row_major> a;
        wmma::load_matrix_sync(a, sA + stripe * 16 * LDA + k, LDA);
        #pragma unroll
        for (int j = 0; j < 2; j++) {
            wmma::fragment<wmma::matrix_b, 16, 16, 16, __half, wmma::row_major> b;
            wmma::load_matrix_sync(b, sB + k * LDB + colHalf * 32 + j * 16, LDB);
            wmma::mma_sync(acc[j], a, b, acc[j]);
        }
    }
    __syncthreads();

    #pragma unroll
    for (int j = 0; j < 2; j++)
        wmma::store_matrix_sync(sC + stripe * 16 * LDC + colHalf * 32 + j * 16,
                                acc[j], LDC, wmma::mem_row_major);
    __syncthreads();

    for (int i = tid; i < 64 * 8; i += 256) {
        int r = i >> 3, q = i & 7;
        int gr = rowBase + r;
        if (gr < N_NODES) {
            const float* src = &sC[r * LDC + q * 8];
            union { __half2 h[4]; uint4 u; } p;
            p.h[0] = __floats2half2_rn(src[0], src[1]);
            p.h[1] = __floats2half2_rn(src[2], src[3]);
            p.h[2] = __floats2half2_rn(src[4], src[5]);
            p.h[3] = __floats2half2_rn(src[6], src[7]);
            ((uint4*)O)[(size_t)gr * 8 + q] = p.u;
        }
    }
}

// ---------------- final aggregation (1 node/warp, fp32 out, deeper MLP) ----
__global__ __launch_bounds__(256)
void k_agg_final(const __half* __restrict__ HW, const float* __restrict__ bias,
                 float* __restrict__ O) {
    int node = (blockIdx.x * blockDim.x + threadIdx.x) >> 5;
    int lane = threadIdx.x & 31;
    if (node >= N_NODES) return;

    const __half2* __restrict__ hw2 = (const __half2*)HW;
    float2 s = gather_node<4>(hw2, node, lane);
    float2 b = __ldg(&((const float2*)bias)[lane]);
    ((float2*)O)[(size_t)node * 32 + lane] = make_float2(s.x + b.x, s.y + b.y);
}

// ---------------- launch ----------------
extern "C" void kernel_launch(void* const* d_in, const int* in_sizes, int n_in,
                              void* d_out, int out_size) {
    const float* x    = (const float*)d_in[0];
    const int*   esrc = (const int*)  d_in[1];
    const int*   edst = (const int*)  d_in[2];
    const float* W1   = (const float*)d_in[3];
    const float* b1   = (const float*)d_in[4];
    const float* W2   = (const float*)d_in[5];
    const float* b2   = (const float*)d_in[6];
    const float* W3   = (const float*)d_in[7];
    const float* b3   = (const float*)d_in[8];
    float* out = (float*)d_out;

    void* p_hw_v;  cudaGetSymbolAddress(&p_hw_v,  g_hw);
    void* p_hw2_v; cudaGetSymbolAddress(&p_hw2_v, g_hw2);
    void* p_cur_v; cudaGetSymbolAddress(&p_cur_v, g_cursor);
    void* p_w2h_v; cudaGetSymbolAddress(&p_w2h_v, g_W2h);
    void* p_w3h_v; cudaGetSymbolAddress(&p_w3h_v, g_W3h);
    __half* p_hw  = (__half*)p_hw_v;
    __half* p_hw2 = (__half*)p_hw2_v;
    __half* p_w2h = (__half*)p_w2h_v;
    __half* p_w3h = (__half*)p_w3h_v;

    static cudaStream_t s2 = nullptr;
    static cudaEvent_t evFork = nullptr, evJoin = nullptr;
    if (!s2) {
        cudaStreamCreateWithFlags(&s2, cudaStreamNonBlocking);
        cudaEventCreateWithFlags(&evFork, cudaEventDisableTiming);
        cudaEventCreateWithFlags(&evJoin, cudaEventDisableTiming);
    }

    const int smem128 = 128 * 136 * 2 + 128 * 72 * 2;  // 53,248 B
    const int smemF   = 64 * 72 * 4;                    // 18,432 B
    cudaFuncSetAttribute(k_transform_mma128, cudaFuncAttributeMaxDynamicSharedMemorySize, smem128);
    cudaFuncSetAttribute(k_agg_transform,    cudaFuncAttributeMaxDynamicSharedMemorySize, smemF);

    const int tgrid128 = (N_NODES + 127) / 128;   // 782 (layer-1)
    const int tgrid    = (N_NODES + 63) / 64;     // 1563 (fused layers)
    const int agrid    = (N_NODES + 7) / 8;

    // ---- fork immediately: side stream does memset + W2/W3 prep + scatter,
    //      main stream does layer-1 transform (self-converts W1) ----
    cudaEventRecord(evFork, 0);
    cudaStreamWaitEvent(s2, evFork, 0);

    cudaMemsetAsync(p_cur_v, 0, N_NODES * sizeof(int), s2);
    k_prep23<<<(HID * HID + 255) / 256, 256, 0, s2>>>(W2, W3);
    k_scatter<<<(N_EDGES / 4 + 255) / 256, 256, 0, s2>>>(esrc, edst);
    cudaEventRecord(evJoin, s2);

    k_transform_mma128<<<tgrid128, 512, smem128>>>(x, W1, p_hw);

    cudaStreamWaitEvent(0, evJoin, 0);   // join before first aggregation

    // layer 2: agg(hw,+b1,relu) -> @W2 -> hw2
    k_agg_transform<<<tgrid, 256, smemF>>>(p_hw, b1, p_w2h, p_hw2);
    // layer 3: agg(hw2,+b2,relu) -> @W3 -> hw
    k_agg_transform<<<tgrid, 256, smemF>>>(p_hw2, b2, p_w3h, p_hw);
    // final: agg(hw) + b3 -> out (fp32)
    k_agg_final<<<agrid, 256>>>(p_hw, b3, out);
}